// round 1
// baseline (speedup 1.0000x reference)
#include <cuda_runtime.h>

#define HID 50
#define NPTS 8192
#define NPARA 5000
#define WARPS_PER_BLOCK 8
#define THREADS (WARPS_PER_BLOCK * 32)

// shared layout (floats)
#define OFF_WIN 0
#define OFF_BIN 150
#define OFF_WH  200
#define OFF_BH  10200
#define OFF_WO  10400
#define OFF_BO  10500
#define OFF_STATE 10504                 // 16B aligned (10504 % 4 == 0)
#define STATE_STRIDE 400                // 50 units * 8 floats per warp
#define OFF_OUT8 (OFF_STATE + WARPS_PER_BLOCK * STATE_STRIDE)   // 13704
#define OFF_PART (OFF_OUT8 + WARPS_PER_BLOCK * 8)               // 13768
#define SMEM_FLOATS (OFF_PART + WARPS_PER_BLOCK * 6)            // 13816
#define SMEM_BYTES (SMEM_FLOATS * 4)                            // 55264

__device__ double g_sums[6];

// tanh(z) and sech^2(z) via sigmoid: r = 1/(e^{2z}+1); h = 1-2r; 1-h^2 = 4r(1-r)
__device__ __forceinline__ void tanh_s(float z, float& h, float& s) {
    float e = __expf(2.0f * z);
    float r = __fdividef(1.0f, e + 1.0f);
    h = 1.0f - 2.0f * r;
    s = 4.0f * r * (1.0f - r);
}

__global__ void zero_kernel() {
    if (threadIdx.x < 6) g_sums[threadIdx.x] = 0.0;
}

__global__ void __launch_bounds__(THREADS) pinn_kernel(
    const float* __restrict__ x,
    const float* __restrict__ W_in, const float* __restrict__ b_in,
    const float* __restrict__ W_hid, const float* __restrict__ b_hid,
    const float* __restrict__ W_out, const float* __restrict__ b_out)
{
    extern __shared__ float sm[];
    const int tid = threadIdx.x;

    for (int i = tid; i < 150;   i += THREADS) sm[OFF_WIN + i] = W_in[i];
    for (int i = tid; i < 50;    i += THREADS) sm[OFF_BIN + i] = b_in[i];
    for (int i = tid; i < 10000; i += THREADS) sm[OFF_WH  + i] = W_hid[i];
    for (int i = tid; i < 200;   i += THREADS) sm[OFF_BH  + i] = b_hid[i];
    for (int i = tid; i < 100;   i += THREADS) sm[OFF_WO  + i] = W_out[i];
    if (tid < 2) sm[OFF_BO + tid] = b_out[tid];
    __syncthreads();

    const int warp = tid >> 5;
    const int lane = tid & 31;
    const int point = blockIdx.x * WARPS_PER_BLOCK + warp;
    float* st = sm + OFF_STATE + warp * STATE_STRIDE;

    const float x0 = x[point * 3 + 0];
    const float x1 = x[point * 3 + 1];
    const float x2 = x[point * 3 + 2];

    // ---- input layer: z = x @ W_in + b_in; first derivs are W_in rows; z'' = 0
    #pragma unroll
    for (int o = 0; o < 2; o++) {
        int j = lane + 32 * o;
        if (j < HID) {
            float w0 = sm[OFF_WIN + j];
            float w1 = sm[OFF_WIN + 50 + j];
            float w2 = sm[OFF_WIN + 100 + j];
            float z = sm[OFF_BIN + j] + x0 * w0 + x1 * w1 + x2 * w2;
            float h, s; tanh_s(z, h, s);
            float d0  = s * w0;                 // d/dx
            float dd0 = -2.0f * h * d0 * w0;    // d2/dx2
            float d1  = s * w1;                 // d/dy
            float dd1 = -2.0f * h * d1 * w1;    // d2/dy2
            float d2  = s * w2;                 // d/dt
            float* p = st + j * 8;
            p[0] = h; p[1] = d0; p[2] = dd0; p[3] = d1; p[4] = dd1; p[5] = d2;
        }
    }
    __syncwarp();

    // ---- 4 hidden layers: 6-channel matvec + tanh chain rule
    const int j1 = lane;
    const int j2 = lane + 32;
    const bool has2 = (j2 < HID);

    for (int l = 0; l < 4; l++) {
        const float* Wl = sm + OFF_WH + l * 2500;
        const float* bl = sm + OFF_BH + l * 50;

        float a00 = bl[j1],              a01 = has2 ? bl[j2] : 0.0f;
        float a10 = 0.f, a11 = 0.f;
        float a20 = 0.f, a21 = 0.f;
        float a30 = 0.f, a31 = 0.f;
        float a40 = 0.f, a41 = 0.f;
        float a50 = 0.f, a51 = 0.f;

        #pragma unroll
        for (int k = 0; k < HID; k++) {
            float4 h03 = *(const float4*)(st + k * 8);       // ch0..3 (broadcast)
            float2 h45 = *(const float2*)(st + k * 8 + 4);   // ch4..5 (broadcast)
            float w1 = Wl[k * 50 + j1];
            float w2 = has2 ? Wl[k * 50 + j2] : 0.0f;
            a00 = fmaf(h03.x, w1, a00); a01 = fmaf(h03.x, w2, a01);
            a10 = fmaf(h03.y, w1, a10); a11 = fmaf(h03.y, w2, a11);
            a20 = fmaf(h03.z, w1, a20); a21 = fmaf(h03.z, w2, a21);
            a30 = fmaf(h03.w, w1, a30); a31 = fmaf(h03.w, w2, a31);
            a40 = fmaf(h45.x, w1, a40); a41 = fmaf(h45.x, w2, a41);
            a50 = fmaf(h45.y, w1, a50); a51 = fmaf(h45.y, w2, a51);
        }
        __syncwarp();   // all reads of old state complete before overwrite
        {
            float h, s; tanh_s(a00, h, s);
            float d0  = s * a10;
            float dd0 = fmaf(-2.0f * h * d0, a10, s * a20);
            float d1  = s * a30;
            float dd1 = fmaf(-2.0f * h * d1, a30, s * a40);
            float d2  = s * a50;
            float* p = st + j1 * 8;
            p[0] = h; p[1] = d0; p[2] = dd0; p[3] = d1; p[4] = dd1; p[5] = d2;
        }
        if (has2) {
            float h, s; tanh_s(a01, h, s);
            float d0  = s * a11;
            float dd0 = fmaf(-2.0f * h * d0, a11, s * a21);
            float d1  = s * a31;
            float dd1 = fmaf(-2.0f * h * d1, a31, s * a41);
            float d2  = s * a51;
            float* p = st + j2 * 8;
            p[0] = h; p[1] = d0; p[2] = dd0; p[3] = d1; p[4] = dd1; p[5] = d2;
        }
        __syncwarp();
    }

    // ---- output layer: need channels {0,2,4,5} x outputs {u,v} = 8 dot products
    if (lane < 8) {
        int ch = (lane >> 1) * 2;        // 0,2,4,6
        if (ch == 6) ch = 5;             // -> 0,2,4,5
        int o = lane & 1;
        float acc0 = (ch == 0) ? sm[OFF_BO + o] : 0.0f;
        float acc1 = 0.0f;
        #pragma unroll
        for (int k = 0; k < HID; k += 2) {
            acc0 = fmaf(st[k * 8 + ch],       sm[OFF_WO + k * 2 + o],       acc0);
            acc1 = fmaf(st[(k + 1) * 8 + ch], sm[OFF_WO + (k + 1) * 2 + o], acc1);
        }
        sm[OFF_OUT8 + warp * 8 + lane] = acc0 + acc1;
    }
    __syncwarp();

    if (lane == 0) {
        const float* o8 = sm + OFF_OUT8 + warp * 8;
        float u  = o8[0], v   = o8[1];
        float uxx = o8[2], vxx = o8[3];
        float uyy = o8[4], vyy = o8[5];
        float ut  = o8[6], vt  = o8[7];
        float Q  = u * u + v * v;
        float A1 = vt - 0.5f * uxx - 0.5f * vyy - Q * u + v;
        float A2 = ut + 0.5f * vxx - 0.5f * uyy + Q * v + u;
        float B1 = uyy, B2 = vyy;
        float C1 = Q * v, C2 = Q * u;
        float* pp = sm + OFF_PART + warp * 6;
        pp[0] = A1 * A1 + A2 * A2;
        pp[1] = B1 * B1 + B2 * B2;
        pp[2] = C1 * C1 + C2 * C2;
        pp[3] = A2 * B2 - A1 * B1;
        pp[4] = A1 * C1 + A2 * C2;
        pp[5] = B1 * C1 - B2 * C2;
    }
    __syncthreads();

    if (tid < 6) {
        double s = 0.0;
        #pragma unroll
        for (int w = 0; w < WARPS_PER_BLOCK; w++)
            s += (double)sm[OFF_PART + w * 6 + tid];
        atomicAdd(&g_sums[tid], s);
    }
}

__global__ void finalize_kernel(const float* __restrict__ para, float* __restrict__ out) {
    int p = blockIdx.x * blockDim.x + threadIdx.x;
    if (p >= NPARA) return;
    double a = (double)para[p * 3 + 0];
    double c = (double)para[p * 3 + 2];
    double r = g_sums[0]
             + 0.25 * a * a * g_sums[1]
             + c * c * g_sums[2]
             + a * g_sums[3]
             - 2.0 * c * g_sums[4]
             + a * c * g_sums[5];
    out[p] = (float)(r * (1.0 / (double)NPTS));
}

extern "C" void kernel_launch(void* const* d_in, const int* in_sizes, int n_in,
                              void* d_out, int out_size) {
    const float* x     = (const float*)d_in[0];
    const float* para  = (const float*)d_in[1];
    const float* W_in  = (const float*)d_in[2];
    const float* b_in  = (const float*)d_in[3];
    const float* W_hid = (const float*)d_in[4];
    const float* b_hid = (const float*)d_in[5];
    const float* W_out = (const float*)d_in[6];
    const float* b_out = (const float*)d_in[7];
    float* out = (float*)d_out;

    cudaFuncSetAttribute(pinn_kernel, cudaFuncAttributeMaxDynamicSharedMemorySize, SMEM_BYTES);

    zero_kernel<<<1, 32>>>();
    pinn_kernel<<<NPTS / WARPS_PER_BLOCK, THREADS, SMEM_BYTES>>>(
        x, W_in, b_in, W_hid, b_hid, W_out, b_out);
    finalize_kernel<<<(NPARA + 255) / 256, 256>>>(para, out);
}